// round 1
// baseline (speedup 1.0000x reference)
#include <cuda_runtime.h>
#include <math.h>

// Problem constants
#define BATCH 32
#define CHAN  4
#define Hn    512
#define Wn    512

// Output layout (flattened tuple, fp32 elements):
//   transformed: [0, 33554432)
//   mat:         [33554432, 33554720)
//   inv_mat:     [33554720, 33555008)
//   grid:        [33555008, 50332224)
//   inv_grid:    [50332224, 67109440)
static __device__ __constant__ long long kMatOff  = 33554432LL;
static __device__ __constant__ long long kInvOff  = 33554720LL;
static __device__ __constant__ long long kGridOff = 33555008LL;
static __device__ __constant__ long long kIGridOff= 50332224LL;

__global__ void build_mats_kernel(const float* __restrict__ fc2,
                                  float* __restrict__ out) {
    int b = threadIdx.x;
    if (b >= BATCH) return;
    const float PI = 3.14159265358979323846f;

    float f0 = fc2[b * 7 + 0];
    float f1 = fc2[b * 7 + 1];
    float f2 = fc2[b * 7 + 2];
    float f3 = fc2[b * 7 + 3];
    float f4 = fc2[b * 7 + 4];
    float f5 = fc2[b * 7 + 5];
    float f6 = fc2[b * 7 + 6];

    float theta = fminf(fmaxf(f0 * 0.3f, -1.0f), 1.0f) * PI;
    float sx    = fminf(fmaxf(f1 * 0.3f + 1.0f, 0.0f), 5.0f);
    float sy    = fminf(fmaxf(f2 * 0.3f + 1.0f, 0.0f), 5.0f);
    float tx    = f3 * 0.3f;
    float ty    = f4 * 0.3f;
    float shxy  = fminf(fmaxf(f5 * 0.3f, -1.0f), 1.0f) * PI;
    float shyx  = fminf(fmaxf(f6 * 0.3f, -1.0f), 1.0f) * PI;

    float c, s;
    __sincosf(theta, &s, &c);
    // use precise versions to match fp32 reference closely
    c = cosf(theta);
    s = sinf(theta);

    // mat = trn @ shr @ scl @ rot
    // scl@rot = [[sx*c, -sx*s],[sy*s, sy*c]]
    float m00 = sx * c + shxy * sy * s;
    float m01 = -sx * s + shxy * sy * c;
    float m10 = shyx * sx * c + sy * s;
    float m11 = -shyx * sx * s + sy * c;

    // affine inverse
    float det  = m00 * m11 - m01 * m10;
    float rdet = 1.0f / det;
    float i00 =  m11 * rdet;
    float i01 = -m01 * rdet;
    float i10 = -m10 * rdet;
    float i11 =  m00 * rdet;
    float i02 = (m01 * ty - m11 * tx) * rdet;
    float i12 = (m10 * tx - m00 * ty) * rdet;

    float* M = out + kMatOff + (long long)b * 9;
    M[0] = m00; M[1] = m01; M[2] = tx;
    M[3] = m10; M[4] = m11; M[5] = ty;
    M[6] = 0.0f; M[7] = 0.0f; M[8] = 1.0f;

    float* I = out + kInvOff + (long long)b * 9;
    I[0] = i00; I[1] = i01; I[2] = i02;
    I[3] = i10; I[4] = i11; I[5] = i12;
    I[6] = 0.0f; I[7] = 0.0f; I[8] = 1.0f;
}

// One block = one (batch, row). 256 threads x 2 pixels = 512 = W.
__global__ __launch_bounds__(256)
void affine_main_kernel(const float* __restrict__ src,
                        float* __restrict__ out) {
    const int h = blockIdx.x;
    const int b = blockIdx.y;
    const int tid = threadIdx.x;

    __shared__ float sm[12]; // m00 m01 m02 m10 m11 m12 | i00 i01 i02 i10 i11 i12
    if (tid < 6) {
        sm[tid]     = out[kMatOff + (long long)b * 9 + tid];
        sm[tid + 6] = out[kInvOff + (long long)b * 9 + tid];
    }
    __syncthreads();

    const float m00 = sm[0], m01 = sm[1], m02 = sm[2];
    const float m10 = sm[3], m11 = sm[4], m12 = sm[5];
    const float i00 = sm[6], i01 = sm[7], i02 = sm[8];
    const float i10 = sm[9], i11 = sm[10], i12 = sm[11];

    const float y = (2.0f * (float)h + 1.0f) * (1.0f / (float)Hn) - 1.0f;
    const int w0 = tid * 2;

    const float x0p = (2.0f * (float)w0 + 1.0f) * (1.0f / (float)Wn) - 1.0f;
    const float x1p = (2.0f * (float)(w0 + 1) + 1.0f) * (1.0f / (float)Wn) - 1.0f;

    // forward grid (used for sampling) and inverse grid
    float gx0 = m00 * x0p + m01 * y + m02;
    float gy0 = m10 * x0p + m11 * y + m12;
    float gx1 = m00 * x1p + m01 * y + m02;
    float gy1 = m10 * x1p + m11 * y + m12;

    float hx0 = i00 * x0p + i01 * y + i02;
    float hy0 = i10 * x0p + i11 * y + i12;
    float hx1 = i00 * x1p + i01 * y + i02;
    float hy1 = i10 * x1p + i11 * y + i12;

    const long long pixBase = (((long long)b * Hn + h) * Wn + w0);

    // grid / inv_grid: float4 stores (2 pixels x 2 comps)
    {
        float4 g = make_float4(gx0, gy0, gx1, gy1);
        float4 ig = make_float4(hx0, hy0, hx1, hy1);
        *reinterpret_cast<float4*>(out + kGridOff + pixBase * 2) = g;
        *reinterpret_cast<float4*>(out + kIGridOff + pixBase * 2) = ig;
    }

    // Bilinear sampling (zero padding), 2 pixels x 4 channels.
    // ix = ((gx+1)*W - 1)*0.5 = gx*256 + 255.5
    float acc[2][CHAN];

    #pragma unroll
    for (int k = 0; k < 2; k++) {
        float gx = k ? gx1 : gx0;
        float gy = k ? gy1 : gy0;
        float ix = gx * ((float)Wn * 0.5f) + ((float)Wn - 1.0f) * 0.5f;
        float iy = gy * ((float)Hn * 0.5f) + ((float)Hn - 1.0f) * 0.5f;
        float x0f = floorf(ix), y0f = floorf(iy);
        float wx = ix - x0f, wy = iy - y0f;
        int xi0 = (int)x0f, yi0 = (int)y0f;
        int xi1 = xi0 + 1,  yi1 = yi0 + 1;

        float vx0 = (xi0 >= 0 && xi0 < Wn) ? 1.0f : 0.0f;
        float vx1 = (xi1 >= 0 && xi1 < Wn) ? 1.0f : 0.0f;
        float vy0 = (yi0 >= 0 && yi0 < Hn) ? 1.0f : 0.0f;
        float vy1 = (yi1 >= 0 && yi1 < Hn) ? 1.0f : 0.0f;

        int cx0 = min(max(xi0, 0), Wn - 1);
        int cx1 = min(max(xi1, 0), Wn - 1);
        int cy0 = min(max(yi0, 0), Hn - 1);
        int cy1 = min(max(yi1, 0), Hn - 1);

        float w00 = (1.0f - wx) * (1.0f - wy) * vx0 * vy0;
        float w01 = wx * (1.0f - wy) * vx1 * vy0;
        float w10 = (1.0f - wx) * wy * vx0 * vy1;
        float w11 = wx * wy * vx1 * vy1;

        long long o00 = (long long)cy0 * Wn + cx0;
        long long o01 = (long long)cy0 * Wn + cx1;
        long long o10 = (long long)cy1 * Wn + cx0;
        long long o11 = (long long)cy1 * Wn + cx1;

        #pragma unroll
        for (int c = 0; c < CHAN; c++) {
            const float* img = src + (((long long)b * CHAN + c) * Hn) * Wn;
            float v00 = __ldg(img + o00);
            float v01 = __ldg(img + o01);
            float v10 = __ldg(img + o10);
            float v11 = __ldg(img + o11);
            acc[k][c] = v00 * w00 + v01 * w01 + v10 * w10 + v11 * w11;
        }
    }

    #pragma unroll
    for (int c = 0; c < CHAN; c++) {
        long long toff = (((long long)b * CHAN + c) * Hn + h) * Wn + w0;
        float2 t = make_float2(acc[0][c], acc[1][c]);
        *reinterpret_cast<float2*>(out + toff) = t;
    }
}

extern "C" void kernel_launch(void* const* d_in, const int* in_sizes, int n_in,
                              void* d_out, int out_size) {
    const float* src = (const float*)d_in[0];
    const float* fc2 = (const float*)d_in[1];
    float* out = (float*)d_out;

    build_mats_kernel<<<1, 32>>>(fc2, out);

    dim3 grid(Hn, BATCH);
    affine_main_kernel<<<grid, 256>>>(src, out);
}

// round 2
// speedup vs baseline: 2.1042x; 2.1042x over previous
#include <cuda_runtime.h>
#include <math.h>

// Problem constants
#define BATCH 32
#define CHAN  4
#define Hn    512
#define Wn    512

// Output layout (flattened tuple, fp32 elements):
//   transformed: [0, 33554432)
//   mat:         [33554432, 33554720)
//   inv_mat:     [33554720, 33555008)
//   grid:        [33555008, 50332224)
//   inv_grid:    [50332224, 67109440)
static __device__ __constant__ long long kMatOff  = 33554432LL;
static __device__ __constant__ long long kInvOff  = 33554720LL;
static __device__ __constant__ long long kGridOff = 33555008LL;
static __device__ __constant__ long long kIGridOff= 50332224LL;

__global__ void build_mats_kernel(const float* __restrict__ fc2,
                                  float* __restrict__ out) {
    int b = threadIdx.x;
    if (b >= BATCH) return;
    const float PI = 3.14159265358979323846f;

    float f0 = fc2[b * 7 + 0];
    float f1 = fc2[b * 7 + 1];
    float f2 = fc2[b * 7 + 2];
    float f3 = fc2[b * 7 + 3];
    float f4 = fc2[b * 7 + 4];
    float f5 = fc2[b * 7 + 5];
    float f6 = fc2[b * 7 + 6];

    float theta = fminf(fmaxf(f0 * 0.3f, -1.0f), 1.0f) * PI;
    float sx    = fminf(fmaxf(f1 * 0.3f + 1.0f, 0.0f), 5.0f);
    float sy    = fminf(fmaxf(f2 * 0.3f + 1.0f, 0.0f), 5.0f);
    float tx    = f3 * 0.3f;
    float ty    = f4 * 0.3f;
    float shxy  = fminf(fmaxf(f5 * 0.3f, -1.0f), 1.0f) * PI;
    float shyx  = fminf(fmaxf(f6 * 0.3f, -1.0f), 1.0f) * PI;

    float c = cosf(theta);
    float s = sinf(theta);

    // mat = trn @ shr @ scl @ rot
    float m00 = sx * c + shxy * sy * s;
    float m01 = -sx * s + shxy * sy * c;
    float m10 = shyx * sx * c + sy * s;
    float m11 = -shyx * sx * s + sy * c;

    // affine inverse
    float det  = m00 * m11 - m01 * m10;
    float rdet = 1.0f / det;
    float i00 =  m11 * rdet;
    float i01 = -m01 * rdet;
    float i10 = -m10 * rdet;
    float i11 =  m00 * rdet;
    float i02 = (m01 * ty - m11 * tx) * rdet;
    float i12 = (m10 * tx - m00 * ty) * rdet;

    float* M = out + kMatOff + (long long)b * 9;
    M[0] = m00; M[1] = m01; M[2] = tx;
    M[3] = m10; M[4] = m11; M[5] = ty;
    M[6] = 0.0f; M[7] = 0.0f; M[8] = 1.0f;

    float* I = out + kInvOff + (long long)b * 9;
    I[0] = i00; I[1] = i01; I[2] = i02;
    I[3] = i10; I[4] = i11; I[5] = i12;
    I[6] = 0.0f; I[7] = 0.0f; I[8] = 1.0f;
}

// 2D-tiled main kernel.
// Block: (8, 32) threads = 256. Each thread handles a 2x2 pixel quad.
// Block tile: 16(x) x 64(y) pixels. Warp (8x4 threads) footprint: 16x8 pixels
// -> compact 2D source footprint per warp -> far fewer L1 wavefronts per gather.
__global__ __launch_bounds__(256)
void affine_main_kernel(const float* __restrict__ src,
                        float* __restrict__ out) {
    const int b  = blockIdx.z;
    const int x0 = blockIdx.x * 16 + threadIdx.x * 2;  // pixel x of quad
    const int y0 = blockIdx.y * 64 + threadIdx.y * 2;  // pixel y of quad

    __shared__ float sm[12];
    {
        int t = threadIdx.y * 8 + threadIdx.x;
        if (t < 6) {
            sm[t]     = out[kMatOff + (long long)b * 9 + t];
            sm[t + 6] = out[kInvOff + (long long)b * 9 + t];
        }
    }
    __syncthreads();

    const float m00 = sm[0], m01 = sm[1], m02 = sm[2];
    const float m10 = sm[3], m11 = sm[4], m12 = sm[5];
    const float i00 = sm[6], i01 = sm[7], i02 = sm[8];
    const float i10 = sm[9], i11 = sm[10], i12 = sm[11];

    // normalized coords
    const float xp0 = (2.0f * (float)x0 + 1.0f) * (1.0f / (float)Wn) - 1.0f;
    const float xp1 = xp0 + 2.0f / (float)Wn;
    const float yp0 = (2.0f * (float)y0 + 1.0f) * (1.0f / (float)Hn) - 1.0f;
    const float yp1 = yp0 + 2.0f / (float)Hn;

    float gx[2][2], gy[2][2], hx[2][2], hy[2][2];
    #pragma unroll
    for (int r = 0; r < 2; r++) {
        float yp = r ? yp1 : yp0;
        #pragma unroll
        for (int c = 0; c < 2; c++) {
            float xp = c ? xp1 : xp0;
            gx[r][c] = fmaf(m00, xp, fmaf(m01, yp, m02));
            gy[r][c] = fmaf(m10, xp, fmaf(m11, yp, m12));
            hx[r][c] = fmaf(i00, xp, fmaf(i01, yp, i02));
            hy[r][c] = fmaf(i10, xp, fmaf(i11, yp, i12));
        }
    }

    // grid / inv_grid stores: float4 per row of the quad (2 px * 2 comps)
    #pragma unroll
    for (int r = 0; r < 2; r++) {
        long long pix = (((long long)b * Hn + (y0 + r)) * Wn + x0);
        float4 g  = make_float4(gx[r][0], gy[r][0], gx[r][1], gy[r][1]);
        float4 ig = make_float4(hx[r][0], hy[r][0], hx[r][1], hy[r][1]);
        *reinterpret_cast<float4*>(out + kGridOff  + pix * 2) = g;
        *reinterpret_cast<float4*>(out + kIGridOff + pix * 2) = ig;
    }

    // Bilinear sampling (zero padding), 4 pixels x 4 channels.
    float acc[2][2][CHAN];

    const float* srcb = src + ((long long)b * CHAN) * Hn * Wn;
    const long long plane = (long long)Hn * Wn;

    #pragma unroll
    for (int r = 0; r < 2; r++) {
        #pragma unroll
        for (int q = 0; q < 2; q++) {
            float ix = gx[r][q] * ((float)Wn * 0.5f) + ((float)Wn - 1.0f) * 0.5f;
            float iy = gy[r][q] * ((float)Hn * 0.5f) + ((float)Hn - 1.0f) * 0.5f;
            float x0f = floorf(ix), y0f = floorf(iy);
            float wx = ix - x0f, wy = iy - y0f;
            int xi0 = (int)x0f, yi0 = (int)y0f;
            int xi1 = xi0 + 1,  yi1 = yi0 + 1;

            float vx0 = (xi0 >= 0 && xi0 < Wn) ? 1.0f : 0.0f;
            float vx1 = (xi1 >= 0 && xi1 < Wn) ? 1.0f : 0.0f;
            float vy0 = (yi0 >= 0 && yi0 < Hn) ? 1.0f : 0.0f;
            float vy1 = (yi1 >= 0 && yi1 < Hn) ? 1.0f : 0.0f;

            int cx0 = min(max(xi0, 0), Wn - 1);
            int cx1 = min(max(xi1, 0), Wn - 1);
            int cy0 = min(max(yi0, 0), Hn - 1);
            int cy1 = min(max(yi1, 0), Hn - 1);

            float w00 = (1.0f - wx) * (1.0f - wy) * vx0 * vy0;
            float w01 = wx * (1.0f - wy) * vx1 * vy0;
            float w10 = (1.0f - wx) * wy * vx0 * vy1;
            float w11 = wx * wy * vx1 * vy1;

            long long o00 = (long long)cy0 * Wn + cx0;
            long long o01 = (long long)cy0 * Wn + cx1;
            long long o10 = (long long)cy1 * Wn + cx0;
            long long o11 = (long long)cy1 * Wn + cx1;

            #pragma unroll
            for (int c = 0; c < CHAN; c++) {
                const float* img = srcb + c * plane;
                float v00 = __ldg(img + o00);
                float v01 = __ldg(img + o01);
                float v10 = __ldg(img + o10);
                float v11 = __ldg(img + o11);
                acc[r][q][c] = v00 * w00 + v01 * w01 + v10 * w10 + v11 * w11;
            }
        }
    }

    // transformed stores: float2 per (channel, row)
    #pragma unroll
    for (int c = 0; c < CHAN; c++) {
        #pragma unroll
        for (int r = 0; r < 2; r++) {
            long long toff = (((long long)b * CHAN + c) * Hn + (y0 + r)) * Wn + x0;
            *reinterpret_cast<float2*>(out + toff) =
                make_float2(acc[r][0][c], acc[r][1][c]);
        }
    }
}

extern "C" void kernel_launch(void* const* d_in, const int* in_sizes, int n_in,
                              void* d_out, int out_size) {
    const float* src = (const float*)d_in[0];
    const float* fc2 = (const float*)d_in[1];
    float* out = (float*)d_out;

    build_mats_kernel<<<1, 32>>>(fc2, out);

    dim3 grid(Wn / 16, Hn / 64, BATCH);
    dim3 block(8, 32);
    affine_main_kernel<<<grid, block>>>(src, out);
}

// round 3
// speedup vs baseline: 2.2719x; 1.0797x over previous
#include <cuda_runtime.h>
#include <math.h>

// Problem constants
#define BATCH 32
#define CHAN  4
#define Hn    512
#define Wn    512

// Output layout (flattened tuple, fp32 elements):
//   transformed: [0, 33554432)
//   mat:         [33554432, 33554720)
//   inv_mat:     [33554720, 33555008)
//   grid:        [33555008, 50332224)
//   inv_grid:    [50332224, 67109440)
#define kMatOff   33554432
#define kInvOff   33554720
#define kGridOff  33555008LL
#define kIGridOff 50332224LL

__global__ void build_mats_kernel(const float* __restrict__ fc2,
                                  float* __restrict__ out) {
    int b = threadIdx.x;
    if (b >= BATCH) return;
    const float PI = 3.14159265358979323846f;

    float f0 = fc2[b * 7 + 0];
    float f1 = fc2[b * 7 + 1];
    float f2 = fc2[b * 7 + 2];
    float f3 = fc2[b * 7 + 3];
    float f4 = fc2[b * 7 + 4];
    float f5 = fc2[b * 7 + 5];
    float f6 = fc2[b * 7 + 6];

    float theta = fminf(fmaxf(f0 * 0.3f, -1.0f), 1.0f) * PI;
    float sx    = fminf(fmaxf(f1 * 0.3f + 1.0f, 0.0f), 5.0f);
    float sy    = fminf(fmaxf(f2 * 0.3f + 1.0f, 0.0f), 5.0f);
    float tx    = f3 * 0.3f;
    float ty    = f4 * 0.3f;
    float shxy  = fminf(fmaxf(f5 * 0.3f, -1.0f), 1.0f) * PI;
    float shyx  = fminf(fmaxf(f6 * 0.3f, -1.0f), 1.0f) * PI;

    float c = cosf(theta);
    float s = sinf(theta);

    // mat = trn @ shr @ scl @ rot
    float m00 = sx * c + shxy * sy * s;
    float m01 = -sx * s + shxy * sy * c;
    float m10 = shyx * sx * c + sy * s;
    float m11 = -shyx * sx * s + sy * c;

    // affine inverse
    float det  = m00 * m11 - m01 * m10;
    float rdet = 1.0f / det;
    float i00 =  m11 * rdet;
    float i01 = -m01 * rdet;
    float i10 = -m10 * rdet;
    float i11 =  m00 * rdet;
    float i02 = (m01 * ty - m11 * tx) * rdet;
    float i12 = (m10 * tx - m00 * ty) * rdet;

    float* M = out + kMatOff + b * 9;
    M[0] = m00; M[1] = m01; M[2] = tx;
    M[3] = m10; M[4] = m11; M[5] = ty;
    M[6] = 0.0f; M[7] = 0.0f; M[8] = 1.0f;

    float* I = out + kInvOff + b * 9;
    I[0] = i00; I[1] = i01; I[2] = i02;
    I[3] = i10; I[4] = i11; I[5] = i12;
    I[6] = 0.0f; I[7] = 0.0f; I[8] = 1.0f;
}

// 1 pixel per thread. Block (8, 32) = 8x32 pixel tile.
// Warp = 8x4 pixel footprint -> each gather instruction's 32 lanes span only
// ~(1 + 8|m10| + 4|m11|) source rows -> minimal L1 wavefronts per instruction.
__global__ __launch_bounds__(256)
void affine_main_kernel(const float* __restrict__ src,
                        float* __restrict__ out) {
    const int b = blockIdx.z;
    const int x = blockIdx.x * 8  + threadIdx.x;
    const int y = blockIdx.y * 32 + threadIdx.y;

    __shared__ float sm[12];
    {
        int t = threadIdx.y * 8 + threadIdx.x;
        if (t < 6) {
            sm[t]     = out[kMatOff + b * 9 + t];
            sm[t + 6] = out[kInvOff + b * 9 + t];
        }
    }
    __syncthreads();

    const float m00 = sm[0], m01 = sm[1], m02 = sm[2];
    const float m10 = sm[3], m11 = sm[4], m12 = sm[5];
    const float i00 = sm[6], i01 = sm[7], i02 = sm[8];
    const float i10 = sm[9], i11 = sm[10], i12 = sm[11];

    const float xp = (2.0f * (float)x + 1.0f) * (1.0f / (float)Wn) - 1.0f;
    const float yp = (2.0f * (float)y + 1.0f) * (1.0f / (float)Hn) - 1.0f;

    const float gx = fmaf(m00, xp, fmaf(m01, yp, m02));
    const float gy = fmaf(m10, xp, fmaf(m11, yp, m12));
    const float hx = fmaf(i00, xp, fmaf(i01, yp, i02));
    const float hy = fmaf(i10, xp, fmaf(i11, yp, i12));

    const long long pix = ((long long)b * Hn + y) * Wn + x;
    *reinterpret_cast<float2*>(out + kGridOff  + pix * 2) = make_float2(gx, gy);
    *reinterpret_cast<float2*>(out + kIGridOff + pix * 2) = make_float2(hx, hy);

    // Bilinear sample (zero padding), 4 corners x 4 channels.
    const float ix = gx * ((float)Wn * 0.5f) + ((float)Wn - 1.0f) * 0.5f;
    const float iy = gy * ((float)Hn * 0.5f) + ((float)Hn - 1.0f) * 0.5f;
    const float x0f = floorf(ix), y0f = floorf(iy);
    const float wx = ix - x0f, wy = iy - y0f;
    const int xi0 = (int)x0f, yi0 = (int)y0f;
    const int xi1 = xi0 + 1,  yi1 = yi0 + 1;

    const float vx0 = (xi0 >= 0 && xi0 < Wn) ? 1.0f : 0.0f;
    const float vx1 = (xi1 >= 0 && xi1 < Wn) ? 1.0f : 0.0f;
    const float vy0 = (yi0 >= 0 && yi0 < Hn) ? 1.0f : 0.0f;
    const float vy1 = (yi1 >= 0 && yi1 < Hn) ? 1.0f : 0.0f;

    const int cx0 = min(max(xi0, 0), Wn - 1);
    const int cx1 = min(max(xi1, 0), Wn - 1);
    const int cy0 = min(max(yi0, 0), Hn - 1);
    const int cy1 = min(max(yi1, 0), Hn - 1);

    const float w00 = (1.0f - wx) * (1.0f - wy) * vx0 * vy0;
    const float w01 = wx * (1.0f - wy) * vx1 * vy0;
    const float w10 = (1.0f - wx) * wy * vx0 * vy1;
    const float w11 = wx * wy * vx1 * vy1;

    const int o00 = cy0 * Wn + cx0;
    const int o01 = cy0 * Wn + cx1;
    const int o10 = cy1 * Wn + cx0;
    const int o11 = cy1 * Wn + cx1;

    const int plane = Hn * Wn;
    const float* img0 = src + ((long long)b * CHAN) * plane;

    float res[CHAN];
    #pragma unroll
    for (int c = 0; c < CHAN; c++) {
        const float* img = img0 + c * plane;
        float v00 = __ldg(img + o00);
        float v01 = __ldg(img + o01);
        float v10 = __ldg(img + o10);
        float v11 = __ldg(img + o11);
        res[c] = v00 * w00 + v01 * w01 + v10 * w10 + v11 * w11;
    }

    #pragma unroll
    for (int c = 0; c < CHAN; c++) {
        long long toff = (((long long)b * CHAN + c) * Hn + y) * Wn + x;
        out[toff] = res[c];
    }
}

extern "C" void kernel_launch(void* const* d_in, const int* in_sizes, int n_in,
                              void* d_out, int out_size) {
    const float* src = (const float*)d_in[0];
    const float* fc2 = (const float*)d_in[1];
    float* out = (float*)d_out;

    build_mats_kernel<<<1, 32>>>(fc2, out);

    dim3 grid(Wn / 8, Hn / 32, BATCH);
    dim3 block(8, 32);
    affine_main_kernel<<<grid, block>>>(src, out);
}

// round 4
// speedup vs baseline: 2.3941x; 1.0538x over previous
#include <cuda_runtime.h>
#include <cuda_fp16.h>
#include <math.h>

// Problem constants
#define BATCH 32
#define CHAN  4
#define Hn    512
#define Wn    512
#define PLANE (Hn * Wn)

// Output layout (flattened tuple, fp32 elements):
//   transformed: [0, 33554432)
//   mat:         [33554432, 33554720)
//   inv_mat:     [33554720, 33555008)
//   grid:        [33555008, 50332224)
//   inv_grid:    [50332224, 67109440)
#define kMatOff   33554432
#define kInvOff   33554720
#define kGridOff  33555008LL
#define kIGridOff 50332224LL

// NHWC fp16x4 packed copy of src: 32*512*512 px * 8B = 64 MB.
__device__ uint2 g_pack[BATCH * PLANE];

__global__ void build_mats_kernel(const float* __restrict__ fc2,
                                  float* __restrict__ out) {
    int b = threadIdx.x;
    if (b >= BATCH) return;
    const float PI = 3.14159265358979323846f;

    float f0 = fc2[b * 7 + 0];
    float f1 = fc2[b * 7 + 1];
    float f2 = fc2[b * 7 + 2];
    float f3 = fc2[b * 7 + 3];
    float f4 = fc2[b * 7 + 4];
    float f5 = fc2[b * 7 + 5];
    float f6 = fc2[b * 7 + 6];

    float theta = fminf(fmaxf(f0 * 0.3f, -1.0f), 1.0f) * PI;
    float sx    = fminf(fmaxf(f1 * 0.3f + 1.0f, 0.0f), 5.0f);
    float sy    = fminf(fmaxf(f2 * 0.3f + 1.0f, 0.0f), 5.0f);
    float tx    = f3 * 0.3f;
    float ty    = f4 * 0.3f;
    float shxy  = fminf(fmaxf(f5 * 0.3f, -1.0f), 1.0f) * PI;
    float shyx  = fminf(fmaxf(f6 * 0.3f, -1.0f), 1.0f) * PI;

    float c = cosf(theta);
    float s = sinf(theta);

    // mat = trn @ shr @ scl @ rot
    float m00 = sx * c + shxy * sy * s;
    float m01 = -sx * s + shxy * sy * c;
    float m10 = shyx * sx * c + sy * s;
    float m11 = -shyx * sx * s + sy * c;

    // affine inverse
    float det  = m00 * m11 - m01 * m10;
    float rdet = 1.0f / det;
    float i00 =  m11 * rdet;
    float i01 = -m01 * rdet;
    float i10 = -m10 * rdet;
    float i11 =  m00 * rdet;
    float i02 = (m01 * ty - m11 * tx) * rdet;
    float i12 = (m10 * tx - m00 * ty) * rdet;

    float* M = out + kMatOff + b * 9;
    M[0] = m00; M[1] = m01; M[2] = tx;
    M[3] = m10; M[4] = m11; M[5] = ty;
    M[6] = 0.0f; M[7] = 0.0f; M[8] = 1.0f;

    float* I = out + kInvOff + b * 9;
    I[0] = i00; I[1] = i01; I[2] = i02;
    I[3] = i10; I[4] = i11; I[5] = i12;
    I[6] = 0.0f; I[7] = 0.0f; I[8] = 1.0f;
}

// NCHW fp32 -> NHWC fp16x4. Fully coalesced both sides; DRAM-bound.
__global__ __launch_bounds__(256)
void pack_kernel(const float* __restrict__ src) {
    int idx = blockIdx.x * 256 + threadIdx.x;  // linear over (b, y, x)
    int b = idx >> 18;
    const float* s = src + (long long)b * CHAN * PLANE + (idx & (PLANE - 1));
    float v0 = __ldg(s);
    float v1 = __ldg(s + PLANE);
    float v2 = __ldg(s + 2 * PLANE);
    float v3 = __ldg(s + 3 * PLANE);
    __half2 lo = __floats2half2_rn(v0, v1);
    __half2 hi = __floats2half2_rn(v2, v3);
    uint2 u;
    u.x = *reinterpret_cast<unsigned*>(&lo);
    u.y = *reinterpret_cast<unsigned*>(&hi);
    g_pack[idx] = u;
}

static __device__ __forceinline__ float4 unpack_h4(uint2 u) {
    __half2 lo = *reinterpret_cast<__half2*>(&u.x);
    __half2 hi = *reinterpret_cast<__half2*>(&u.y);
    float2 a = __half22float2(lo);
    float2 c = __half22float2(hi);
    return make_float4(a.x, a.y, c.x, c.y);
}

// 1 pixel per thread. Block (8, 32) = 8x32 tile; warp footprint 8x4.
// Gathers are 4x LDG.64 from the NHWC fp16x4 buffer (all channels per load).
__global__ __launch_bounds__(256)
void affine_main_kernel(float* __restrict__ out) {
    const int b = blockIdx.z;
    const int x = blockIdx.x * 8  + threadIdx.x;
    const int y = blockIdx.y * 32 + threadIdx.y;

    __shared__ float sm[12];
    {
        int t = threadIdx.y * 8 + threadIdx.x;
        if (t < 6) {
            sm[t]     = out[kMatOff + b * 9 + t];
            sm[t + 6] = out[kInvOff + b * 9 + t];
        }
    }
    __syncthreads();

    const float m00 = sm[0], m01 = sm[1], m02 = sm[2];
    const float m10 = sm[3], m11 = sm[4], m12 = sm[5];
    const float i00 = sm[6], i01 = sm[7], i02 = sm[8];
    const float i10 = sm[9], i11 = sm[10], i12 = sm[11];

    const float xp = (2.0f * (float)x + 1.0f) * (1.0f / (float)Wn) - 1.0f;
    const float yp = (2.0f * (float)y + 1.0f) * (1.0f / (float)Hn) - 1.0f;

    const float gx = fmaf(m00, xp, fmaf(m01, yp, m02));
    const float gy = fmaf(m10, xp, fmaf(m11, yp, m12));
    const float hx = fmaf(i00, xp, fmaf(i01, yp, i02));
    const float hy = fmaf(i10, xp, fmaf(i11, yp, i12));

    const long long pix = ((long long)b * Hn + y) * Wn + x;
    *reinterpret_cast<float2*>(out + kGridOff  + pix * 2) = make_float2(gx, gy);
    *reinterpret_cast<float2*>(out + kIGridOff + pix * 2) = make_float2(hx, hy);

    // Bilinear sample (zero padding) from packed NHWC fp16x4.
    const float ix = gx * ((float)Wn * 0.5f) + ((float)Wn - 1.0f) * 0.5f;
    const float iy = gy * ((float)Hn * 0.5f) + ((float)Hn - 1.0f) * 0.5f;
    const float x0f = floorf(ix), y0f = floorf(iy);
    const float wx = ix - x0f, wy = iy - y0f;
    const int xi0 = (int)x0f, yi0 = (int)y0f;
    const int xi1 = xi0 + 1,  yi1 = yi0 + 1;

    const float vx0 = (xi0 >= 0 && xi0 < Wn) ? 1.0f : 0.0f;
    const float vx1 = (xi1 >= 0 && xi1 < Wn) ? 1.0f : 0.0f;
    const float vy0 = (yi0 >= 0 && yi0 < Hn) ? 1.0f : 0.0f;
    const float vy1 = (yi1 >= 0 && yi1 < Hn) ? 1.0f : 0.0f;

    const int cx0 = min(max(xi0, 0), Wn - 1);
    const int cx1 = min(max(xi1, 0), Wn - 1);
    const int cy0 = min(max(yi0, 0), Hn - 1);
    const int cy1 = min(max(yi1, 0), Hn - 1);

    const float w00 = (1.0f - wx) * (1.0f - wy) * vx0 * vy0;
    const float w01 = wx * (1.0f - wy) * vx1 * vy0;
    const float w10 = (1.0f - wx) * wy * vx0 * vy1;
    const float w11 = wx * wy * vx1 * vy1;

    const uint2* pk = g_pack + (long long)b * PLANE;
    uint2 r00 = __ldg(pk + cy0 * Wn + cx0);
    uint2 r01 = __ldg(pk + cy0 * Wn + cx1);
    uint2 r10 = __ldg(pk + cy1 * Wn + cx0);
    uint2 r11 = __ldg(pk + cy1 * Wn + cx1);

    float4 v00 = unpack_h4(r00);
    float4 v01 = unpack_h4(r01);
    float4 v10 = unpack_h4(r10);
    float4 v11 = unpack_h4(r11);

    float4 res;
    res.x = fmaf(v00.x, w00, fmaf(v01.x, w01, fmaf(v10.x, w10, v11.x * w11)));
    res.y = fmaf(v00.y, w00, fmaf(v01.y, w01, fmaf(v10.y, w10, v11.y * w11)));
    res.z = fmaf(v00.z, w00, fmaf(v01.z, w01, fmaf(v10.z, w10, v11.z * w11)));
    res.w = fmaf(v00.w, w00, fmaf(v01.w, w01, fmaf(v10.w, w10, v11.w * w11)));

    const long long tbase = ((long long)b * CHAN * Hn + y) * Wn + x;
    out[tbase]                       = res.x;
    out[tbase + (long long)PLANE]    = res.y;
    out[tbase + 2LL * PLANE]         = res.z;
    out[tbase + 3LL * PLANE]         = res.w;
}

extern "C" void kernel_launch(void* const* d_in, const int* in_sizes, int n_in,
                              void* d_out, int out_size) {
    const float* src = (const float*)d_in[0];
    const float* fc2 = (const float*)d_in[1];
    float* out = (float*)d_out;

    pack_kernel<<<(BATCH * PLANE) / 256, 256>>>(src);
    build_mats_kernel<<<1, 32>>>(fc2, out);

    dim3 grid(Wn / 8, Hn / 32, BATCH);
    dim3 block(8, 32);
    affine_main_kernel<<<grid, block>>>(out);
}

// round 5
// speedup vs baseline: 2.5096x; 1.0483x over previous
#include <cuda_runtime.h>
#include <cuda_fp16.h>
#include <math.h>

// Problem constants
#define BATCH 32
#define CHAN  4
#define Hn    512
#define Wn    512
#define PLANE (Hn * Wn)

// Output layout (flattened tuple, fp32 elements):
#define kMatOff   33554432
#define kInvOff   33554720
#define kGridOff  33555008LL
#define kIGridOff 50332224LL

// NHWC fp16x4 packed copy of src: 32*512*512 px * 8B = 64 MB.
__device__ uint2 g_pack[BATCH * PLANE];

__global__ void build_mats_kernel(const float* __restrict__ fc2,
                                  float* __restrict__ out) {
    int b = threadIdx.x;
    if (b >= BATCH) return;
    const float PI = 3.14159265358979323846f;

    float f0 = fc2[b * 7 + 0];
    float f1 = fc2[b * 7 + 1];
    float f2 = fc2[b * 7 + 2];
    float f3 = fc2[b * 7 + 3];
    float f4 = fc2[b * 7 + 4];
    float f5 = fc2[b * 7 + 5];
    float f6 = fc2[b * 7 + 6];

    float theta = fminf(fmaxf(f0 * 0.3f, -1.0f), 1.0f) * PI;
    float sx    = fminf(fmaxf(f1 * 0.3f + 1.0f, 0.0f), 5.0f);
    float sy    = fminf(fmaxf(f2 * 0.3f + 1.0f, 0.0f), 5.0f);
    float tx    = f3 * 0.3f;
    float ty    = f4 * 0.3f;
    float shxy  = fminf(fmaxf(f5 * 0.3f, -1.0f), 1.0f) * PI;
    float shyx  = fminf(fmaxf(f6 * 0.3f, -1.0f), 1.0f) * PI;

    float c = cosf(theta);
    float s = sinf(theta);

    float m00 = sx * c + shxy * sy * s;
    float m01 = -sx * s + shxy * sy * c;
    float m10 = shyx * sx * c + sy * s;
    float m11 = -shyx * sx * s + sy * c;

    float det  = m00 * m11 - m01 * m10;
    float rdet = 1.0f / det;
    float i00 =  m11 * rdet;
    float i01 = -m01 * rdet;
    float i10 = -m10 * rdet;
    float i11 =  m00 * rdet;
    float i02 = (m01 * ty - m11 * tx) * rdet;
    float i12 = (m10 * tx - m00 * ty) * rdet;

    float* M = out + kMatOff + b * 9;
    M[0] = m00; M[1] = m01; M[2] = tx;
    M[3] = m10; M[4] = m11; M[5] = ty;
    M[6] = 0.0f; M[7] = 0.0f; M[8] = 1.0f;

    float* I = out + kInvOff + b * 9;
    I[0] = i00; I[1] = i01; I[2] = i02;
    I[3] = i10; I[4] = i11; I[5] = i12;
    I[6] = 0.0f; I[7] = 0.0f; I[8] = 1.0f;
}

// NCHW fp32 -> NHWC fp16x4, 4 pixels per thread (float4 loads, uint4 stores).
__global__ __launch_bounds__(256)
void pack_kernel(const float* __restrict__ src) {
    int t = blockIdx.x * 256 + threadIdx.x;
    int idx4 = t * 4;                  // first pixel index (b,y,x linear)
    int b    = idx4 >> 18;
    int rem  = idx4 & (PLANE - 1);

    const float* base = src + (long long)b * CHAN * PLANE + rem;
    float4 v0 = __ldg(reinterpret_cast<const float4*>(base));
    float4 v1 = __ldg(reinterpret_cast<const float4*>(base + PLANE));
    float4 v2 = __ldg(reinterpret_cast<const float4*>(base + 2 * PLANE));
    float4 v3 = __ldg(reinterpret_cast<const float4*>(base + 3 * PLANE));

    uint2 p[4];
    {
        __half2 a, bb;
        a = __floats2half2_rn(v0.x, v1.x); bb = __floats2half2_rn(v2.x, v3.x);
        p[0].x = *reinterpret_cast<unsigned*>(&a); p[0].y = *reinterpret_cast<unsigned*>(&bb);
        a = __floats2half2_rn(v0.y, v1.y); bb = __floats2half2_rn(v2.y, v3.y);
        p[1].x = *reinterpret_cast<unsigned*>(&a); p[1].y = *reinterpret_cast<unsigned*>(&bb);
        a = __floats2half2_rn(v0.z, v1.z); bb = __floats2half2_rn(v2.z, v3.z);
        p[2].x = *reinterpret_cast<unsigned*>(&a); p[2].y = *reinterpret_cast<unsigned*>(&bb);
        a = __floats2half2_rn(v0.w, v1.w); bb = __floats2half2_rn(v2.w, v3.w);
        p[3].x = *reinterpret_cast<unsigned*>(&a); p[3].y = *reinterpret_cast<unsigned*>(&bb);
    }
    uint4* dst = reinterpret_cast<uint4*>(g_pack + idx4);
    dst[0] = make_uint4(p[0].x, p[0].y, p[1].x, p[1].y);
    dst[1] = make_uint4(p[2].x, p[2].y, p[3].x, p[3].y);
}

static __device__ __forceinline__ float4 unpack_h4(uint2 u) {
    __half2 lo = *reinterpret_cast<__half2*>(&u.x);
    __half2 hi = *reinterpret_cast<__half2*>(&u.y);
    float2 a = __half22float2(lo);
    float2 c = __half22float2(hi);
    return make_float4(a.x, a.y, c.x, c.y);
}

// Block tile: 32(x) x 8(y) pixels, 256 threads, 1 px/thread.
// Compute phase: warps laid out as 8x4 pixel footprints (compact gathers).
// Store phase: threads remapped row-major; transformed staged via smem,
// grid/igrid recomputed (affine is cheap) -> all stores are full-width float4.
__global__ __launch_bounds__(256)
void affine_main_kernel(float* __restrict__ out) {
    const int b  = blockIdx.z;
    const int bx = blockIdx.x * 32;
    const int by = blockIdx.y * 8;
    const int tid  = threadIdx.x;
    const int warp = tid >> 5;
    const int lane = tid & 31;

    __shared__ float sm[12];
    __shared__ float s_t[CHAN][8][32];  // XOR-swizzled columns

    if (tid < 6) {
        sm[tid]     = out[kMatOff + b * 9 + tid];
        sm[tid + 6] = out[kInvOff + b * 9 + tid];
    }
    __syncthreads();

    const float m00 = sm[0], m01 = sm[1], m02 = sm[2];
    const float m10 = sm[3], m11 = sm[4], m12 = sm[5];

    // ---- compute phase: 8x4 warp footprint ----
    {
        const int wx = (warp & 3) * 8;
        const int wy = (warp >> 2) * 4;
        const int lx = lane & 7;
        const int ly = lane >> 3;
        const int cx = wx + lx;          // col in tile
        const int cr = wy + ly;          // row in tile
        const int x = bx + cx;
        const int y = by + cr;

        const float xp = (2.0f * (float)x + 1.0f) * (1.0f / (float)Wn) - 1.0f;
        const float yp = (2.0f * (float)y + 1.0f) * (1.0f / (float)Hn) - 1.0f;

        const float gx = fmaf(m00, xp, fmaf(m01, yp, m02));
        const float gy = fmaf(m10, xp, fmaf(m11, yp, m12));

        const float ix = gx * ((float)Wn * 0.5f) + ((float)Wn - 1.0f) * 0.5f;
        const float iy = gy * ((float)Hn * 0.5f) + ((float)Hn - 1.0f) * 0.5f;
        const float x0f = floorf(ix), y0f = floorf(iy);
        const float wxf = ix - x0f, wyf = iy - y0f;
        const int xi0 = (int)x0f, yi0 = (int)y0f;
        const int xi1 = xi0 + 1,  yi1 = yi0 + 1;

        const float vx0 = (xi0 >= 0 && xi0 < Wn) ? 1.0f : 0.0f;
        const float vx1 = (xi1 >= 0 && xi1 < Wn) ? 1.0f : 0.0f;
        const float vy0 = (yi0 >= 0 && yi0 < Hn) ? 1.0f : 0.0f;
        const float vy1 = (yi1 >= 0 && yi1 < Hn) ? 1.0f : 0.0f;

        const int cx0 = min(max(xi0, 0), Wn - 1);
        const int cx1 = min(max(xi1, 0), Wn - 1);
        const int cy0 = min(max(yi0, 0), Hn - 1);
        const int cy1 = min(max(yi1, 0), Hn - 1);

        const float w00 = (1.0f - wxf) * (1.0f - wyf) * vx0 * vy0;
        const float w01 = wxf * (1.0f - wyf) * vx1 * vy0;
        const float w10 = (1.0f - wxf) * wyf * vx0 * vy1;
        const float w11 = wxf * wyf * vx1 * vy1;

        const uint2* pk = g_pack + (long long)b * PLANE;
        float4 v00 = unpack_h4(__ldg(pk + cy0 * Wn + cx0));
        float4 v01 = unpack_h4(__ldg(pk + cy0 * Wn + cx1));
        float4 v10 = unpack_h4(__ldg(pk + cy1 * Wn + cx0));
        float4 v11 = unpack_h4(__ldg(pk + cy1 * Wn + cx1));

        const int sc = cx ^ ((cr & 3) << 3);  // swizzled column
        s_t[0][cr][sc] = fmaf(v00.x, w00, fmaf(v01.x, w01, fmaf(v10.x, w10, v11.x * w11)));
        s_t[1][cr][sc] = fmaf(v00.y, w00, fmaf(v01.y, w01, fmaf(v10.y, w10, v11.y * w11)));
        s_t[2][cr][sc] = fmaf(v00.z, w00, fmaf(v01.z, w01, fmaf(v10.z, w10, v11.z * w11)));
        s_t[3][cr][sc] = fmaf(v00.w, w00, fmaf(v01.w, w01, fmaf(v10.w, w10, v11.w * w11)));
    }
    __syncthreads();

    // ---- store phase: row-major float4 stores ----
    // transformed: 256 float4s, 1 per thread.
    {
        const int ch  = tid >> 6;
        const int rem = tid & 63;
        const int row = rem >> 3;
        const int q   = rem & 7;
        const int scol = (q * 4) ^ ((row & 3) << 3);
        float4 v = *reinterpret_cast<const float4*>(&s_t[ch][row][scol]);
        long long off = (((long long)b * CHAN + ch) * Hn + (by + row)) * Wn + bx + q * 4;
        *reinterpret_cast<float4*>(out + off) = v;
    }

    // grid / inv_grid: recompute affine; threads 0-127 grid, 128-255 igrid.
    {
        const bool inv = tid >= 128;
        const float a00 = inv ? sm[6]  : m00;
        const float a01 = inv ? sm[7]  : m01;
        const float a02 = inv ? sm[8]  : m02;
        const float a10 = inv ? sm[9]  : m10;
        const float a11 = inv ? sm[10] : m11;
        const float a12 = inv ? sm[11] : m12;

        const int u   = tid & 127;      // pixel-pair index
        const int row = u >> 4;         // 0..7
        const int col = (u & 15) * 2;   // even column 0..30

        const int x = bx + col;
        const int y = by + row;
        const float xp0 = (2.0f * (float)x + 1.0f) * (1.0f / (float)Wn) - 1.0f;
        const float xp1 = xp0 + 2.0f / (float)Wn;
        const float yp  = (2.0f * (float)y + 1.0f) * (1.0f / (float)Hn) - 1.0f;

        float4 g;
        g.x = fmaf(a00, xp0, fmaf(a01, yp, a02));
        g.y = fmaf(a10, xp0, fmaf(a11, yp, a12));
        g.z = fmaf(a00, xp1, fmaf(a01, yp, a02));
        g.w = fmaf(a10, xp1, fmaf(a11, yp, a12));

        const long long pix = ((long long)b * Hn + y) * Wn + x;
        const long long base = inv ? kIGridOff : kGridOff;
        *reinterpret_cast<float4*>(out + base + pix * 2) = g;
    }
}

extern "C" void kernel_launch(void* const* d_in, const int* in_sizes, int n_in,
                              void* d_out, int out_size) {
    const float* src = (const float*)d_in[0];
    const float* fc2 = (const float*)d_in[1];
    float* out = (float*)d_out;

    pack_kernel<<<(BATCH * PLANE) / (256 * 4), 256>>>(src);
    build_mats_kernel<<<1, 32>>>(fc2, out);

    dim3 grid(Wn / 32, Hn / 8, BATCH);
    affine_main_kernel<<<grid, 256>>>(out);
}